// round 1
// baseline (speedup 1.0000x reference)
#include <cuda_runtime.h>
#include <math.h>

#define NN 50000
#define NE 1250000
#define F  64
#define ED 7
#define NL 3

// ---------------- scratch (static device memory; no allocs) ----------------
__device__ float g_feats[4][NN * F];   // feats[0]=emb gather, feats[1..3]=layer outputs
__device__ float g_n1[NN * F];         // h @ w1[0:64]  (per-layer, reused)
__device__ float g_r[NN];              // h . att_r     (per-layer, reused)
__device__ float g_t[NN * F];          // segment_sum(a * xj)
__device__ int   g_rowptr[NN + 1];
__device__ int   g_cursor[NN];
__device__ int   g_counts[NN];
__device__ int   g_srcs[NE];           // src node id, dst-sorted
__device__ float g_eas[NE * ED];       // edge_attr, dst-sorted
__device__ float g_alpha[NE];          // alpha, then exp(alpha - max)

__device__ __forceinline__ float lrelu(float x) { return x > 0.f ? x : 0.01f * x; }

// ---------------- embedding gather ----------------
__global__ void k_gather(const int* __restrict__ x, const float* __restrict__ emb) {
    int i = blockIdx.x * blockDim.x + threadIdx.x;
    if (i >= NN * F) return;
    int n = i >> 6, f = i & 63;
    g_feats[0][i] = emb[(long long)x[n] * F + f];
}

// ---------------- CSR build ----------------
__global__ void k_zero() {
    int i = blockIdx.x * blockDim.x + threadIdx.x;
    if (i < NN) g_counts[i] = 0;
}

__global__ void k_hist(const int* __restrict__ ei) {
    int e = blockIdx.x * blockDim.x + threadIdx.x;
    if (e < NE) atomicAdd(&g_counts[ei[NE + e]], 1);
}

__global__ void k_scan() {  // single block of 1024 threads
    __shared__ int part[1024];
    int t = threadIdx.x;
    const int C = (NN + 1023) / 1024;
    int beg = t * C, end = min(beg + C, NN);
    int s = 0;
    for (int i = beg; i < end; i++) s += g_counts[i];
    part[t] = s;
    __syncthreads();
    if (t == 0) {
        int acc = 0;
        for (int i = 0; i < 1024; i++) { int v = part[i]; part[i] = acc; acc += v; }
        g_rowptr[NN] = acc;
    }
    __syncthreads();
    int acc = part[t];
    for (int i = beg; i < end; i++) {
        g_rowptr[i] = acc;
        g_cursor[i] = acc;
        acc += g_counts[i];
    }
}

__global__ void k_scatter(const int* __restrict__ ei, const float* __restrict__ eattr) {
    int e = blockIdx.x * blockDim.x + threadIdx.x;
    if (e >= NE) return;
    int d = ei[NE + e];
    int pos = atomicAdd(&g_cursor[d], 1);
    g_srcs[pos] = ei[e];
#pragma unroll
    for (int k = 0; k < ED; k++) g_eas[pos * ED + k] = eattr[e * ED + k];
}

// ---------------- per-layer node prep: n1 = h @ w1a ; r = h . att_r ----------------
__global__ void k_prep(int l, const float* __restrict__ w1, const float* __restrict__ ar) {
    __shared__ float s_w[F * F];
    __shared__ float s_ar[F];
    __shared__ float s_h[8][F];
    int tid = threadIdx.x;
    for (int i = tid; i < F * F; i += blockDim.x) s_w[i] = w1[i];  // rows 0..63 of [71,64]
    if (tid < F) s_ar[tid] = ar[tid];
    __syncthreads();
    int warp = tid >> 5, lane = tid & 31;
    int node = blockIdx.x * 8 + warp;
    if (node >= NN) return;
    const float* h = g_feats[l] + node * F;
    s_h[warp][lane]      = h[lane];
    s_h[warp][lane + 32] = h[lane + 32];
    __syncwarp();
    float a0 = 0.f, a1 = 0.f;
#pragma unroll 8
    for (int k = 0; k < F; k++) {
        float hv = s_h[warp][k];
        a0 += hv * s_w[k * F + lane];
        a1 += hv * s_w[k * F + lane + 32];
    }
    g_n1[node * F + lane]      = a0;
    g_n1[node * F + lane + 32] = a1;
    float p = s_h[warp][lane] * s_ar[lane] + s_h[warp][lane + 32] * s_ar[lane + 32];
#pragma unroll
    for (int o = 16; o; o >>= 1) p += __shfl_xor_sync(0xffffffffu, p, o);
    if (lane == 0) g_r[node] = p;
}

// ---------------- edge kernel: warp per dst node, softmax attention + weighted sum ----------------
__global__ void k_edge(const float* __restrict__ w1, const float* __restrict__ al) {
    __shared__ float s_wb[ED * F];  // w1 rows 64..70 (edge_attr part)
    __shared__ float s_al[F];
    int tid = threadIdx.x;
    for (int i = tid; i < ED * F; i += blockDim.x) s_wb[i] = w1[F * F + i];
    if (tid < F) s_al[tid] = al[tid];
    __syncthreads();
    int warp = tid >> 5, lane = tid & 31;
    int node = blockIdx.x * 8 + warp;
    if (node >= NN) return;
    int beg = g_rowptr[node], end = g_rowptr[node + 1];
    int f0 = lane, f1 = lane + 32;
    float al0 = s_al[f0], al1 = s_al[f1];
    float ri = g_r[node];
    float maxv = -INFINITY;

    // pass A: alpha per edge (all lanes see reduced value), running max
    for (int p = beg; p < end; p++) {
        int j = g_srcs[p];
        const float* ea = g_eas + p * ED;
        float c0 = 0.f, c1 = 0.f;
#pragma unroll
        for (int k = 0; k < ED; k++) {
            float ev = ea[k];
            c0 += ev * s_wb[k * F + f0];
            c1 += ev * s_wb[k * F + f1];
        }
        float x0 = lrelu(g_n1[j * F + f0] + c0);
        float x1 = lrelu(g_n1[j * F + f1] + c1);
        float part = x0 * al0 + x1 * al1;
#pragma unroll
        for (int o = 16; o; o >>= 1) part += __shfl_xor_sync(0xffffffffu, part, o);
        float alpha = lrelu(part + ri);
        if (lane == 0) g_alpha[p] = alpha;
        maxv = fmaxf(maxv, alpha);
    }
    __syncwarp();

    // exp pass: overwrite alpha with exp(alpha - max), accumulate denom
    float dsum = 0.f;
    for (int p = beg + lane; p < end; p += 32) {
        float w = __expf(g_alpha[p] - maxv);
        g_alpha[p] = w;
        dsum += w;
    }
#pragma unroll
    for (int o = 16; o; o >>= 1) dsum += __shfl_xor_sync(0xffffffffu, dsum, o);
    float inv = 1.f / (dsum + 1e-16f);
    __syncwarp();

    // pass B: recompute xj (n1 gather is L2-resident), accumulate a * xj
    float a0 = 0.f, a1 = 0.f;
    for (int p = beg; p < end; p++) {
        int j = g_srcs[p];
        const float* ea = g_eas + p * ED;
        float c0 = 0.f, c1 = 0.f;
#pragma unroll
        for (int k = 0; k < ED; k++) {
            float ev = ea[k];
            c0 += ev * s_wb[k * F + f0];
            c1 += ev * s_wb[k * F + f1];
        }
        float x0 = lrelu(g_n1[j * F + f0] + c0);
        float x1 = lrelu(g_n1[j * F + f1] + c1);
        float w = g_alpha[p] * inv;
        a0 += w * x0;
        a1 += w * x1;
    }
    g_t[node * F + f0] = a0;
    g_t[node * F + f1] = a1;
}

// ---------------- node update: h_next = relu(t @ w2 + b) ----------------
__global__ void k_update(int l, const float* __restrict__ w2, const float* __restrict__ b) {
    __shared__ float s_w[F * F];
    __shared__ float s_b[F];
    __shared__ float s_t[8][F];
    int tid = threadIdx.x;
    for (int i = tid; i < F * F; i += blockDim.x) s_w[i] = w2[i];
    if (tid < F) s_b[tid] = b[tid];
    __syncthreads();
    int warp = tid >> 5, lane = tid & 31;
    int node = blockIdx.x * 8 + warp;
    if (node >= NN) return;
    s_t[warp][lane]      = g_t[node * F + lane];
    s_t[warp][lane + 32] = g_t[node * F + lane + 32];
    __syncwarp();
    float a0 = s_b[lane], a1 = s_b[lane + 32];
#pragma unroll 8
    for (int k = 0; k < F; k++) {
        float tv = s_t[warp][k];
        a0 += tv * s_w[k * F + lane];
        a1 += tv * s_w[k * F + lane + 32];
    }
    g_feats[l + 1][node * F + lane]      = fmaxf(a0, 0.f);
    g_feats[l + 1][node * F + lane + 32] = fmaxf(a1, 0.f);
}

// ---------------- head: sigmoid(relu(hcat @ fc1 + b1) @ fc2 + b2) ----------------
__global__ void k_head(const float* __restrict__ fc1, const float* __restrict__ b1,
                       const float* __restrict__ fc2, const float* __restrict__ b2,
                       float* __restrict__ out) {
    __shared__ float s_fc1[256 * 20];
    __shared__ float s_fc2[20];
    __shared__ float s_b1[20];
    __shared__ float s_h[8][256];
    int tid = threadIdx.x;
    for (int i = tid; i < 256 * 20; i += blockDim.x) s_fc1[i] = fc1[i];
    if (tid < 20) { s_fc2[tid] = fc2[tid]; s_b1[tid] = b1[tid]; }
    __syncthreads();
    int warp = tid >> 5, lane = tid & 31;
    int node = blockIdx.x * 8 + warp;
    if (node >= NN) return;
#pragma unroll
    for (int c = 0; c < 4; c++) {
        s_h[warp][c * 64 + lane]      = g_feats[c][node * F + lane];
        s_h[warp][c * 64 + lane + 32] = g_feats[c][node * F + lane + 32];
    }
    __syncwarp();
    float z = 0.f;
    if (lane < 20) {
        z = s_b1[lane];
        for (int f = 0; f < 256; f++) z += s_h[warp][f] * s_fc1[f * 20 + lane];
        z = fmaxf(z, 0.f) * s_fc2[lane];
    }
#pragma unroll
    for (int o = 16; o; o >>= 1) z += __shfl_xor_sync(0xffffffffu, z, o);
    if (lane == 0) out[node] = 1.f / (1.f + __expf(-(z + b2[0])));
}

// ---------------- launch ----------------
extern "C" void kernel_launch(void* const* d_in, const int* in_sizes, int n_in,
                              void* d_out, int out_size) {
    const int*   x     = (const int*)  d_in[0];
    const int*   ei    = (const int*)  d_in[1];   // [2, E]
    const float* eattr = (const float*)d_in[2];   // [E, 7]
    const float* emb   = (const float*)d_in[3];   // [VOCAB, 64]
    const float* lin1  = (const float*)d_in[4];   // [3, 71, 64]
    const float* attl  = (const float*)d_in[5];   // [3, 64]
    const float* attr_ = (const float*)d_in[6];   // [3, 64]
    const float* lin2  = (const float*)d_in[7];   // [3, 64, 64]
    const float* gb    = (const float*)d_in[8];   // [3, 64]
    const float* fc1   = (const float*)d_in[9];   // [256, 20]
    const float* fb1   = (const float*)d_in[10];  // [20]
    const float* fc2   = (const float*)d_in[11];  // [20, 1]
    const float* fb2   = (const float*)d_in[12];  // [1]
    float* out = (float*)d_out;

    k_gather<<<(NN * F + 255) / 256, 256>>>(x, emb);
    k_zero<<<(NN + 255) / 256, 256>>>();
    k_hist<<<(NE + 255) / 256, 256>>>(ei);
    k_scan<<<1, 1024>>>();
    k_scatter<<<(NE + 255) / 256, 256>>>(ei, eattr);

    int nb = (NN + 7) / 8;  // warp per node, 8 warps/block
    for (int l = 0; l < NL; l++) {
        k_prep<<<nb, 256>>>(l, lin1 + l * 71 * F, attr_ + l * F);
        k_edge<<<nb, 256>>>(lin1 + l * 71 * F, attl + l * F);
        k_update<<<nb, 256>>>(l, lin2 + l * F * F, gb + l * F);
    }
    k_head<<<nb, 256>>>(fc1, fb1, fc2, fb2, out);
}

// round 2
// speedup vs baseline: 2.0601x; 2.0601x over previous
#include <cuda_runtime.h>
#include <math.h>

#define NN 50000
#define NE 1250000
#define F  64
#define ED 7
#define NL 3
#define SCAN_BS 512
#define NSB ((NN + SCAN_BS - 1) / SCAN_BS)   // 98

// ---------------- scratch (static device memory; no allocs) ----------------
__device__ float g_feats[4][NN * F];   // feats[0]=emb gather, feats[1..3]=layer outputs
__device__ float g_n1[NN * F];         // h @ w1[0:64]  (per-layer, reused)
__device__ float g_r[NN];              // h . att_r     (per-layer, reused)
__device__ float g_t[NN * F];          // normalized segment_sum(a * xj)
__device__ int   g_rowptr[NN + 1];
__device__ int   g_cursor[NN];
__device__ int   g_counts[NN];
__device__ int   g_bsums[NSB];
__device__ int2  g_se[NE];             // (src, edge_id), dst-sorted

__device__ __forceinline__ float lrelu(float x) { return fmaxf(x, 0.01f * x); }

// ---------------- embedding gather (float4) ----------------
__global__ void k_gather(const int* __restrict__ x, const float* __restrict__ emb) {
    int i = blockIdx.x * blockDim.x + threadIdx.x;
    if (i >= NN * 16) return;
    int n = i >> 4, q = i & 15;
    reinterpret_cast<float4*>(g_feats[0])[(long long)n * 16 + q] =
        reinterpret_cast<const float4*>(emb)[(long long)x[n] * 16 + q];
}

// ---------------- CSR build ----------------
__global__ void k_zero() {
    int i = blockIdx.x * blockDim.x + threadIdx.x;
    if (i < NN) g_counts[i] = 0;
}

__global__ void k_hist(const int* __restrict__ ei) {
    int e = blockIdx.x * blockDim.x + threadIdx.x;
    if (e < NE) atomicAdd(&g_counts[ei[NE + e]], 1);
}

// block-level inclusive scan; writes per-block exclusive result + block total
__global__ void k_scan_a() {
    __shared__ int sh[SCAN_BS];
    int t = threadIdx.x;
    int i = blockIdx.x * SCAN_BS + t;
    int v = (i < NN) ? g_counts[i] : 0;
    sh[t] = v;
    __syncthreads();
#pragma unroll
    for (int o = 1; o < SCAN_BS; o <<= 1) {
        int u = (t >= o) ? sh[t - o] : 0;
        __syncthreads();
        sh[t] += u;
        __syncthreads();
    }
    if (i < NN) g_rowptr[i] = sh[t] - v;           // exclusive within block
    if (t == SCAN_BS - 1) g_bsums[blockIdx.x] = sh[t];
}

__global__ void k_scan_b() {  // 1 block of 128 threads scans NSB=98 block sums
    __shared__ int sh[128];
    int t = threadIdx.x;
    int v = (t < NSB) ? g_bsums[t] : 0;
    sh[t] = v;
    __syncthreads();
#pragma unroll
    for (int o = 1; o < 128; o <<= 1) {
        int u = (t >= o) ? sh[t - o] : 0;
        __syncthreads();
        sh[t] += u;
        __syncthreads();
    }
    if (t < NSB) g_bsums[t] = sh[t] - v;           // exclusive
}

__global__ void k_scan_c() {
    int i = blockIdx.x * SCAN_BS + threadIdx.x;
    if (i < NN) {
        int r = g_rowptr[i] + g_bsums[blockIdx.x];
        g_rowptr[i] = r;
        g_cursor[i] = r;
    }
    if (i == 0) g_rowptr[NN] = NE;
}

__global__ void k_scatter(const int* __restrict__ ei) {
    int e = blockIdx.x * blockDim.x + threadIdx.x;
    if (e >= NE) return;
    int d = ei[NE + e];
    int pos = atomicAdd(&g_cursor[d], 1);
    g_se[pos] = make_int2(ei[e], e);
}

// ---------------- per-layer node prep: n1 = h @ w1a ; r = h . att_r ----------------
__global__ void k_prep(int l, const float* __restrict__ w1, const float* __restrict__ ar) {
    __shared__ float s_w[F * F];
    __shared__ float s_ar[F];
    __shared__ float s_h[8][F];
    int tid = threadIdx.x;
    for (int i = tid; i < F * F; i += blockDim.x) s_w[i] = w1[i];  // rows 0..63 of [71,64]
    if (tid < F) s_ar[tid] = ar[tid];
    __syncthreads();
    int warp = tid >> 5, lane = tid & 31;
    int node = blockIdx.x * 8 + warp;
    if (node >= NN) return;
    const float* h = g_feats[l] + node * F;
    s_h[warp][lane]      = h[lane];
    s_h[warp][lane + 32] = h[lane + 32];
    __syncwarp();
    float a0 = 0.f, a1 = 0.f;
#pragma unroll 8
    for (int k = 0; k < F; k++) {
        float hv = s_h[warp][k];
        a0 += hv * s_w[k * F + lane];
        a1 += hv * s_w[k * F + lane + 32];
    }
    g_n1[node * F + lane]      = a0;
    g_n1[node * F + lane + 32] = a1;
    float p = s_h[warp][lane] * s_ar[lane] + s_h[warp][lane + 32] * s_ar[lane + 32];
#pragma unroll
    for (int o = 16; o; o >>= 1) p += __shfl_xor_sync(0xffffffffu, p, o);
    if (lane == 0) g_r[node] = p;
}

// ---------------- edge kernel: warp per dst node, single-pass online softmax ----------------
__global__ void k_edge(const float* __restrict__ w1, const float* __restrict__ al,
                       const float* __restrict__ eattr) {
    __shared__ float s_wb[ED * F];  // w1 rows 64..70 (edge_attr part)
    __shared__ float s_al[F];
    int tid = threadIdx.x;
    for (int i = tid; i < ED * F; i += blockDim.x) s_wb[i] = w1[F * F + i];
    if (tid < F) s_al[tid] = al[tid];
    __syncthreads();
    int warp = tid >> 5, lane = tid & 31;
    int node = blockIdx.x * 8 + warp;
    if (node >= NN) return;
    int beg = g_rowptr[node], end = g_rowptr[node + 1];
    int f0 = lane, f1 = lane + 32;
    float al0 = s_al[f0], al1 = s_al[f1];
    float ri = g_r[node];

    float m = -INFINITY, s = 0.f, a0 = 0.f, a1 = 0.f;
    for (int p = beg; p < end; p++) {
        int2 se = g_se[p];
        const float* ea = eattr + (long long)se.y * ED;
        float c0, c1;
        {
            float e0 = ea[0], e1 = ea[1], e2 = ea[2], e3 = ea[3],
                  e4 = ea[4], e5 = ea[5], e6 = ea[6];
            c0 = e0 * s_wb[0 * F + f0] + e1 * s_wb[1 * F + f0] + e2 * s_wb[2 * F + f0]
               + e3 * s_wb[3 * F + f0] + e4 * s_wb[4 * F + f0] + e5 * s_wb[5 * F + f0]
               + e6 * s_wb[6 * F + f0];
            c1 = e0 * s_wb[0 * F + f1] + e1 * s_wb[1 * F + f1] + e2 * s_wb[2 * F + f1]
               + e3 * s_wb[3 * F + f1] + e4 * s_wb[4 * F + f1] + e5 * s_wb[5 * F + f1]
               + e6 * s_wb[6 * F + f1];
        }
        float x0 = lrelu(g_n1[se.x * F + f0] + c0);
        float x1 = lrelu(g_n1[se.x * F + f1] + c1);
        float part = x0 * al0 + x1 * al1;
#pragma unroll
        for (int o = 16; o; o >>= 1) part += __shfl_xor_sync(0xffffffffu, part, o);
        float alpha = lrelu(part + ri);
        if (alpha > m) {                       // warp-uniform branch (~ln(deg) times)
            float corr = __expf(m - alpha);    // first iter: exp(-inf)=0
            s  = s  * corr + 1.f;
            a0 = a0 * corr + x0;
            a1 = a1 * corr + x1;
            m = alpha;
        } else {
            float w = __expf(alpha - m);
            s  += w;
            a0 += w * x0;
            a1 += w * x1;
        }
    }
    float inv = 1.f / (s + 1e-16f);
    g_t[node * F + f0] = a0 * inv;
    g_t[node * F + f1] = a1 * inv;
}

// ---------------- node update: h_next = relu(t @ w2 + b) ----------------
__global__ void k_update(int l, const float* __restrict__ w2, const float* __restrict__ b) {
    __shared__ float s_w[F * F];
    __shared__ float s_b[F];
    __shared__ float s_t[8][F];
    int tid = threadIdx.x;
    for (int i = tid; i < F * F; i += blockDim.x) s_w[i] = w2[i];
    if (tid < F) s_b[tid] = b[tid];
    __syncthreads();
    int warp = tid >> 5, lane = tid & 31;
    int node = blockIdx.x * 8 + warp;
    if (node >= NN) return;
    s_t[warp][lane]      = g_t[node * F + lane];
    s_t[warp][lane + 32] = g_t[node * F + lane + 32];
    __syncwarp();
    float a0 = s_b[lane], a1 = s_b[lane + 32];
#pragma unroll 8
    for (int k = 0; k < F; k++) {
        float tv = s_t[warp][k];
        a0 += tv * s_w[k * F + lane];
        a1 += tv * s_w[k * F + lane + 32];
    }
    g_feats[l + 1][node * F + lane]      = fmaxf(a0, 0.f);
    g_feats[l + 1][node * F + lane + 32] = fmaxf(a1, 0.f);
}

// ---------------- head: sigmoid(relu(hcat @ fc1 + b1) @ fc2 + b2) ----------------
__global__ void k_head(const float* __restrict__ fc1, const float* __restrict__ b1,
                       const float* __restrict__ fc2, const float* __restrict__ b2,
                       float* __restrict__ out) {
    __shared__ float s_fc1[256 * 20];
    __shared__ float s_fc2[20];
    __shared__ float s_b1[20];
    __shared__ float s_h[8][256];
    int tid = threadIdx.x;
    for (int i = tid; i < 256 * 20; i += blockDim.x) s_fc1[i] = fc1[i];
    if (tid < 20) { s_fc2[tid] = fc2[tid]; s_b1[tid] = b1[tid]; }
    __syncthreads();
    int warp = tid >> 5, lane = tid & 31;
    int node = blockIdx.x * 8 + warp;
    if (node >= NN) return;
#pragma unroll
    for (int c = 0; c < 4; c++) {
        s_h[warp][c * 64 + lane]      = g_feats[c][node * F + lane];
        s_h[warp][c * 64 + lane + 32] = g_feats[c][node * F + lane + 32];
    }
    __syncwarp();
    float z = 0.f;
    if (lane < 20) {
        z = s_b1[lane];
        for (int f = 0; f < 256; f++) z += s_h[warp][f] * s_fc1[f * 20 + lane];
        z = fmaxf(z, 0.f) * s_fc2[lane];
    }
#pragma unroll
    for (int o = 16; o; o >>= 1) z += __shfl_xor_sync(0xffffffffu, z, o);
    if (lane == 0) out[node] = 1.f / (1.f + __expf(-(z + b2[0])));
}

// ---------------- launch ----------------
extern "C" void kernel_launch(void* const* d_in, const int* in_sizes, int n_in,
                              void* d_out, int out_size) {
    const int*   x     = (const int*)  d_in[0];
    const int*   ei    = (const int*)  d_in[1];   // [2, E]
    const float* eattr = (const float*)d_in[2];   // [E, 7]
    const float* emb   = (const float*)d_in[3];   // [VOCAB, 64]
    const float* lin1  = (const float*)d_in[4];   // [3, 71, 64]
    const float* attl  = (const float*)d_in[5];   // [3, 64]
    const float* attr_ = (const float*)d_in[6];   // [3, 64]
    const float* lin2  = (const float*)d_in[7];   // [3, 64, 64]
    const float* gb    = (const float*)d_in[8];   // [3, 64]
    const float* fc1   = (const float*)d_in[9];   // [256, 20]
    const float* fb1   = (const float*)d_in[10];  // [20]
    const float* fc2   = (const float*)d_in[11];  // [20, 1]
    const float* fb2   = (const float*)d_in[12];  // [1]
    float* out = (float*)d_out;

    k_gather<<<(NN * 16 + 255) / 256, 256>>>(x, emb);
    k_zero<<<(NN + 255) / 256, 256>>>();
    k_hist<<<(NE + 255) / 256, 256>>>(ei);
    k_scan_a<<<NSB, SCAN_BS>>>();
    k_scan_b<<<1, 128>>>();
    k_scan_c<<<NSB, SCAN_BS>>>();
    k_scatter<<<(NE + 255) / 256, 256>>>(ei);

    int nb = (NN + 7) / 8;  // warp per node, 8 warps/block
    for (int l = 0; l < NL; l++) {
        k_prep<<<nb, 256>>>(l, lin1 + l * 71 * F, attr_ + l * F);
        k_edge<<<nb, 256>>>(lin1 + l * 71 * F, attl + l * F, eattr);
        k_update<<<nb, 256>>>(l, lin2 + l * F * F, gb + l * F);
    }
    k_head<<<nb, 256>>>(fc1, fb1, fc2, fb2, out);
}

// round 3
// speedup vs baseline: 2.2822x; 1.1078x over previous
#include <cuda_runtime.h>
#include <math.h>

#define NN 50000
#define NE 1250000
#define F  64
#define ED 7
#define NL 3
#define SCAN_BS 512
#define NSB ((NN + SCAN_BS - 1) / SCAN_BS)   // 98

// ---------------- scratch (static device memory; no allocs) ----------------
__device__ float g_feats[4][NN * F];   // feats[0]=emb gather, feats[1..3]=layer outputs
__device__ float g_n1[NN * F];         // h @ w1[0:64]  (per-layer, reused)
__device__ float g_r[NN];              // h . att_r     (per-layer, reused)
__device__ float g_t[NN * F];          // normalized segment_sum(a * xj)
__device__ int   g_rowptr[NN + 1];
__device__ int   g_cursor[NN];
__device__ int   g_counts[NN];
__device__ int   g_bsums[NSB];
__device__ int    g_src[NE + 8];        // src node id, dst-sorted (+pad for prefetch)
__device__ float4 g_ea8[2 * NE + 16];   // edge_attr padded to 8 floats, dst-sorted

__device__ __forceinline__ float lrelu(float x) { return fmaxf(x, 0.01f * x); }

// ---------------- embedding gather (float4) ----------------
__global__ void k_gather(const int* __restrict__ x, const float* __restrict__ emb) {
    int i = blockIdx.x * blockDim.x + threadIdx.x;
    if (i >= NN * 16) return;
    int n = i >> 4, q = i & 15;
    reinterpret_cast<float4*>(g_feats[0])[(long long)n * 16 + q] =
        reinterpret_cast<const float4*>(emb)[(long long)x[n] * 16 + q];
}

// ---------------- CSR build ----------------
__global__ void k_zero() {
    int i = blockIdx.x * blockDim.x + threadIdx.x;
    if (i < NN) g_counts[i] = 0;
}

__global__ void k_hist(const int* __restrict__ ei) {
    int e = blockIdx.x * blockDim.x + threadIdx.x;
    if (e < NE) atomicAdd(&g_counts[ei[NE + e]], 1);
}

__global__ void k_scan_a() {
    __shared__ int sh[SCAN_BS];
    int t = threadIdx.x;
    int i = blockIdx.x * SCAN_BS + t;
    int v = (i < NN) ? g_counts[i] : 0;
    sh[t] = v;
    __syncthreads();
#pragma unroll
    for (int o = 1; o < SCAN_BS; o <<= 1) {
        int u = (t >= o) ? sh[t - o] : 0;
        __syncthreads();
        sh[t] += u;
        __syncthreads();
    }
    if (i < NN) g_rowptr[i] = sh[t] - v;           // exclusive within block
    if (t == SCAN_BS - 1) g_bsums[blockIdx.x] = sh[t];
}

__global__ void k_scan_b() {
    __shared__ int sh[128];
    int t = threadIdx.x;
    int v = (t < NSB) ? g_bsums[t] : 0;
    sh[t] = v;
    __syncthreads();
#pragma unroll
    for (int o = 1; o < 128; o <<= 1) {
        int u = (t >= o) ? sh[t - o] : 0;
        __syncthreads();
        sh[t] += u;
        __syncthreads();
    }
    if (t < NSB) g_bsums[t] = sh[t] - v;           // exclusive
}

__global__ void k_scan_c() {
    int i = blockIdx.x * SCAN_BS + threadIdx.x;
    if (i < NN) {
        int r = g_rowptr[i] + g_bsums[blockIdx.x];
        g_rowptr[i] = r;
        g_cursor[i] = r;
    }
    if (i == 0) g_rowptr[NN] = NE;
}

__global__ void k_scatter(const int* __restrict__ ei, const float* __restrict__ eattr) {
    int e = blockIdx.x * blockDim.x + threadIdx.x;
    if (e >= NE) return;
    int d = ei[NE + e];
    int pos = atomicAdd(&g_cursor[d], 1);
    g_src[pos] = ei[e];
    const float* ea = eattr + (long long)e * ED;
    g_ea8[2 * pos]     = make_float4(ea[0], ea[1], ea[2], ea[3]);
    g_ea8[2 * pos + 1] = make_float4(ea[4], ea[5], ea[6], 0.f);
}

// ---------------- per-layer node prep: n1 = h @ w1a ; r = h . att_r ----------------
__global__ void k_prep(int l, const float* __restrict__ w1, const float* __restrict__ ar) {
    __shared__ float s_w[F * F];
    __shared__ float s_ar[F];
    __shared__ float s_h[8][F];
    int tid = threadIdx.x;
    for (int i = tid; i < F * F; i += blockDim.x) s_w[i] = w1[i];  // rows 0..63 of [71,64]
    if (tid < F) s_ar[tid] = ar[tid];
    __syncthreads();
    int warp = tid >> 5, lane = tid & 31;
    int node = blockIdx.x * 8 + warp;
    if (node >= NN) return;
    const float* h = g_feats[l] + node * F;
    s_h[warp][lane]      = h[lane];
    s_h[warp][lane + 32] = h[lane + 32];
    __syncwarp();
    float a0 = 0.f, a1 = 0.f;
#pragma unroll 8
    for (int k = 0; k < F; k++) {
        float hv = s_h[warp][k];
        a0 += hv * s_w[k * F + lane];
        a1 += hv * s_w[k * F + lane + 32];
    }
    g_n1[node * F + lane]      = a0;
    g_n1[node * F + lane + 32] = a1;
    float p = s_h[warp][lane] * s_ar[lane] + s_h[warp][lane + 32] * s_ar[lane + 32];
#pragma unroll
    for (int o = 16; o; o >>= 1) p += __shfl_xor_sync(0xffffffffu, p, o);
    if (lane == 0) g_r[node] = p;
}

// ---------------- edge kernel: warp/node, register weights, pipelined, branchless ----------------
__global__ void k_edge(const float* __restrict__ w1, const float* __restrict__ al) {
    int tid = threadIdx.x;
    int warp = tid >> 5, lane = tid & 31;
    int node = blockIdx.x * 8 + warp;
    if (node >= NN) return;
    int f0 = lane, f1 = lane + 32;

    // hoist edge-attr weight rows (w1[64..70]) + att_l into registers
    const float* wb = w1 + F * F;
    float w00 = wb[0 * F + f0], w01 = wb[0 * F + f1];
    float w10 = wb[1 * F + f0], w11 = wb[1 * F + f1];
    float w20 = wb[2 * F + f0], w21 = wb[2 * F + f1];
    float w30 = wb[3 * F + f0], w31 = wb[3 * F + f1];
    float w40 = wb[4 * F + f0], w41 = wb[4 * F + f1];
    float w50 = wb[5 * F + f0], w51 = wb[5 * F + f1];
    float w60 = wb[6 * F + f0], w61 = wb[6 * F + f1];
    float al0 = al[f0], al1 = al[f1];
    float ri = g_r[node];

    int beg = g_rowptr[node], end = g_rowptr[node + 1];
    float m = -INFINITY, s = 0.f, a0 = 0.f, a1 = 0.f;

    // prime pipeline (arrays padded; safe to read one past end)
    int   src = g_src[beg];
    float4 eA = g_ea8[2 * beg];
    float4 eB = g_ea8[2 * beg + 1];

    for (int p = beg; p < end; p++) {
        // prefetch next edge
        int    nsrc = g_src[p + 1];
        float4 nA   = g_ea8[2 * (p + 1)];
        float4 nB   = g_ea8[2 * (p + 1) + 1];
        // current edge
        float v0 = g_n1[src * F + f0];
        float v1 = g_n1[src * F + f1];
        float c0 = eA.x * w00 + eA.y * w10 + eA.z * w20 + eA.w * w30
                 + eB.x * w40 + eB.y * w50 + eB.z * w60;
        float c1 = eA.x * w01 + eA.y * w11 + eA.z * w21 + eA.w * w31
                 + eB.x * w41 + eB.y * w51 + eB.z * w61;
        float x0 = lrelu(v0 + c0);
        float x1 = lrelu(v1 + c1);
        float part = x0 * al0 + x1 * al1;
#pragma unroll
        for (int o = 16; o; o >>= 1) part += __shfl_xor_sync(0xffffffffu, part, o);
        float alpha = lrelu(part + ri);
        // branchless online softmax
        float newm = fmaxf(m, alpha);
        float corr = __expf(m - newm);
        float w    = __expf(alpha - newm);
        s  = fmaf(s,  corr, w);
        a0 = fmaf(a0, corr, w * x0);
        a1 = fmaf(a1, corr, w * x1);
        m = newm;
        src = nsrc; eA = nA; eB = nB;
    }
    float inv = 1.f / (s + 1e-16f);
    g_t[node * F + f0] = a0 * inv;
    g_t[node * F + f1] = a1 * inv;
}

// ---------------- node update: h_next = relu(t @ w2 + b) ----------------
__global__ void k_update(int l, const float* __restrict__ w2, const float* __restrict__ b) {
    __shared__ float s_w[F * F];
    __shared__ float s_b[F];
    __shared__ float s_t[8][F];
    int tid = threadIdx.x;
    for (int i = tid; i < F * F; i += blockDim.x) s_w[i] = w2[i];
    if (tid < F) s_b[tid] = b[tid];
    __syncthreads();
    int warp = tid >> 5, lane = tid & 31;
    int node = blockIdx.x * 8 + warp;
    if (node >= NN) return;
    s_t[warp][lane]      = g_t[node * F + lane];
    s_t[warp][lane + 32] = g_t[node * F + lane + 32];
    __syncwarp();
    float a0 = s_b[lane], a1 = s_b[lane + 32];
#pragma unroll 8
    for (int k = 0; k < F; k++) {
        float tv = s_t[warp][k];
        a0 += tv * s_w[k * F + lane];
        a1 += tv * s_w[k * F + lane + 32];
    }
    g_feats[l + 1][node * F + lane]      = fmaxf(a0, 0.f);
    g_feats[l + 1][node * F + lane + 32] = fmaxf(a1, 0.f);
}

// ---------------- head: sigmoid(relu(hcat @ fc1 + b1) @ fc2 + b2) ----------------
__global__ void k_head(const float* __restrict__ fc1, const float* __restrict__ b1,
                       const float* __restrict__ fc2, const float* __restrict__ b2,
                       float* __restrict__ out) {
    __shared__ float s_fc1[256 * 20];
    __shared__ float s_fc2[20];
    __shared__ float s_b1[20];
    __shared__ float s_h[8][256];
    int tid = threadIdx.x;
    for (int i = tid; i < 256 * 20; i += blockDim.x) s_fc1[i] = fc1[i];
    if (tid < 20) { s_fc2[tid] = fc2[tid]; s_b1[tid] = b1[tid]; }
    __syncthreads();
    int warp = tid >> 5, lane = tid & 31;
    int node = blockIdx.x * 8 + warp;
    if (node >= NN) return;
#pragma unroll
    for (int c = 0; c < 4; c++) {
        s_h[warp][c * 64 + lane]      = g_feats[c][node * F + lane];
        s_h[warp][c * 64 + lane + 32] = g_feats[c][node * F + lane + 32];
    }
    __syncwarp();
    float z = 0.f;
    if (lane < 20) {
        float z0 = 0.f, z1 = 0.f, z2 = 0.f, z3 = 0.f;
        for (int f = 0; f < 256; f += 4) {
            z0 += s_h[warp][f]     * s_fc1[f * 20 + lane];
            z1 += s_h[warp][f + 1] * s_fc1[(f + 1) * 20 + lane];
            z2 += s_h[warp][f + 2] * s_fc1[(f + 2) * 20 + lane];
            z3 += s_h[warp][f + 3] * s_fc1[(f + 3) * 20 + lane];
        }
        z = s_b1[lane] + (z0 + z1) + (z2 + z3);
        z = fmaxf(z, 0.f) * s_fc2[lane];
    }
#pragma unroll
    for (int o = 16; o; o >>= 1) z += __shfl_xor_sync(0xffffffffu, z, o);
    if (lane == 0) out[node] = 1.f / (1.f + __expf(-(z + b2[0])));
}

// ---------------- launch ----------------
extern "C" void kernel_launch(void* const* d_in, const int* in_sizes, int n_in,
                              void* d_out, int out_size) {
    const int*   x     = (const int*)  d_in[0];
    const int*   ei    = (const int*)  d_in[1];   // [2, E]
    const float* eattr = (const float*)d_in[2];   // [E, 7]
    const float* emb   = (const float*)d_in[3];   // [VOCAB, 64]
    const float* lin1  = (const float*)d_in[4];   // [3, 71, 64]
    const float* attl  = (const float*)d_in[5];   // [3, 64]
    const float* attr_ = (const float*)d_in[6];   // [3, 64]
    const float* lin2  = (const float*)d_in[7];   // [3, 64, 64]
    const float* gb    = (const float*)d_in[8];   // [3, 64]
    const float* fc1   = (const float*)d_in[9];   // [256, 20]
    const float* fb1   = (const float*)d_in[10];  // [20]
    const float* fc2   = (const float*)d_in[11];  // [20, 1]
    const float* fb2   = (const float*)d_in[12];  // [1]
    float* out = (float*)d_out;

    k_gather<<<(NN * 16 + 255) / 256, 256>>>(x, emb);
    k_zero<<<(NN + 255) / 256, 256>>>();
    k_hist<<<(NE + 255) / 256, 256>>>(ei);
    k_scan_a<<<NSB, SCAN_BS>>>();
    k_scan_b<<<1, 128>>>();
    k_scan_c<<<NSB, SCAN_BS>>>();
    k_scatter<<<(NE + 255) / 256, 256>>>(ei, eattr);

    int nb = (NN + 7) / 8;  // warp per node, 8 warps/block
    for (int l = 0; l < NL; l++) {
        k_prep<<<nb, 256>>>(l, lin1 + l * 71 * F, attr_ + l * F);
        k_edge<<<nb, 256>>>(lin1 + l * 71 * F, attl + l * F);
        k_update<<<nb, 256>>>(l, lin2 + l * F * F, gb + l * F);
    }
    k_head<<<nb, 256>>>(fc1, fb1, fc2, fb2, out);
}

// round 4
// speedup vs baseline: 2.5457x; 1.1155x over previous
#include <cuda_runtime.h>
#include <math.h>

#define NN 50000
#define NE 1250000
#define F  64
#define ED 7
#define NL 3
#define SCAN_BS 512
#define NSB ((NN + SCAN_BS - 1) / SCAN_BS)   // 98

// ---------------- scratch (static device memory; no allocs) ----------------
__device__ float g_feats[3][NN * F];   // feats[0..2]; feats[3] lives only in uphead
__device__ float g_n1[NN * F];         // h @ w1[0:64]  (per-layer, reused)
__device__ float g_r[NN];              // h . att_r     (per-layer, reused)
__device__ float g_t[NN * F];          // normalized segment_sum(a * xj)
__device__ int   g_rowptr[NN + 1];
__device__ int   g_cursor[NN];
__device__ int   g_counts[NN];         // zero-initialized at load; re-zeroed in scan_a
__device__ int   g_bsums[NSB];
__device__ int    g_src[NE + 8];       // src node id, dst-sorted (+pad)
__device__ float4 g_ea8[2 * NE + 16];  // edge_attr padded to 8 floats, dst-sorted

__device__ __forceinline__ float lrelu(float x) { return fmaxf(x, 0.01f * x); }

// ---------------- CSR build ----------------
__global__ void k_hist(const int* __restrict__ ei) {
    int e = blockIdx.x * blockDim.x + threadIdx.x;
    if (e < NE) atomicAdd(&g_counts[ei[NE + e]], 1);
}

__global__ void k_scan_a() {
    __shared__ int sh[SCAN_BS];
    int t = threadIdx.x;
    int i = blockIdx.x * SCAN_BS + t;
    int v = (i < NN) ? g_counts[i] : 0;
    if (i < NN) g_counts[i] = 0;                   // re-zero for next replay
    sh[t] = v;
    __syncthreads();
#pragma unroll
    for (int o = 1; o < SCAN_BS; o <<= 1) {
        int u = (t >= o) ? sh[t - o] : 0;
        __syncthreads();
        sh[t] += u;
        __syncthreads();
    }
    if (i < NN) g_rowptr[i] = sh[t] - v;           // exclusive within block
    if (t == SCAN_BS - 1) g_bsums[blockIdx.x] = sh[t];
}

__global__ void k_scan_b() {
    __shared__ int sh[128];
    int t = threadIdx.x;
    int v = (t < NSB) ? g_bsums[t] : 0;
    sh[t] = v;
    __syncthreads();
#pragma unroll
    for (int o = 1; o < 128; o <<= 1) {
        int u = (t >= o) ? sh[t - o] : 0;
        __syncthreads();
        sh[t] += u;
        __syncthreads();
    }
    if (t < NSB) g_bsums[t] = sh[t] - v;           // exclusive
}

__global__ void k_scan_c() {
    int i = blockIdx.x * SCAN_BS + threadIdx.x;
    if (i < NN) {
        int r = g_rowptr[i] + g_bsums[blockIdx.x];
        g_rowptr[i] = r;
        g_cursor[i] = r;
    }
    if (i == 0) g_rowptr[NN] = NE;
}

__global__ void k_scatter(const int* __restrict__ ei, const float* __restrict__ eattr) {
    int e = blockIdx.x * blockDim.x + threadIdx.x;
    if (e >= NE) return;
    int d = ei[NE + e];
    int pos = atomicAdd(&g_cursor[d], 1);
    g_src[pos] = ei[e];
    const float* ea = eattr + (long long)e * ED;
    g_ea8[2 * pos]     = make_float4(ea[0], ea[1], ea[2], ea[3]);
    g_ea8[2 * pos + 1] = make_float4(ea[4], ea[5], ea[6], 0.f);
}

// ---------------- fused gather + prep layer0 ----------------
__global__ void k_gprep(const int* __restrict__ x, const float* __restrict__ emb,
                        const float* __restrict__ w1, const float* __restrict__ ar) {
    __shared__ float s_w[F * F];
    __shared__ float s_ar[F];
    __shared__ float s_h[8][F];
    int tid = threadIdx.x;
    for (int i = tid; i < F * F; i += blockDim.x) s_w[i] = w1[i];
    if (tid < F) s_ar[tid] = ar[tid];
    __syncthreads();
    int warp = tid >> 5, lane = tid & 31;
    int node = blockIdx.x * 8 + warp;
    if (node >= NN) return;
    long long row = (long long)x[node] * F;
    float2 h2 = reinterpret_cast<const float2*>(emb + row)[lane];
    reinterpret_cast<float2*>(&s_h[warp][0])[lane] = h2;
    reinterpret_cast<float2*>(g_feats[0] + node * F)[lane] = h2;
    __syncwarp();
    float a0 = 0.f, a1 = 0.f;
#pragma unroll 16
    for (int k = 0; k < F; k++) {
        float hv = s_h[warp][k];
        float2 wv = reinterpret_cast<const float2*>(s_w + k * F)[lane];
        a0 += hv * wv.x;
        a1 += hv * wv.y;
    }
    reinterpret_cast<float2*>(g_n1 + node * F)[lane] = make_float2(a0, a1);
    float2 ar2 = reinterpret_cast<const float2*>(s_ar)[lane];
    float p = h2.x * ar2.x + h2.y * ar2.y;
#pragma unroll
    for (int o = 16; o; o >>= 1) p += __shfl_xor_sync(0xffffffffu, p, o);
    if (lane == 0) g_r[node] = p;
}

// ---------------- edge kernel: warp/node, no max-subtract, 2-edge ILP ----------------
__global__ void k_edge(const float* __restrict__ w1, const float* __restrict__ al) {
    int tid = threadIdx.x;
    int warp = tid >> 5, lane = tid & 31;
    int node = blockIdx.x * 8 + warp;
    if (node >= NN) return;

    const float* wb = w1 + F * F;  // rows 64..70 (edge_attr part)
    float2 w0 = reinterpret_cast<const float2*>(wb + 0 * F)[lane];
    float2 w1v = reinterpret_cast<const float2*>(wb + 1 * F)[lane];
    float2 w2v = reinterpret_cast<const float2*>(wb + 2 * F)[lane];
    float2 w3v = reinterpret_cast<const float2*>(wb + 3 * F)[lane];
    float2 w4v = reinterpret_cast<const float2*>(wb + 4 * F)[lane];
    float2 w5v = reinterpret_cast<const float2*>(wb + 5 * F)[lane];
    float2 w6v = reinterpret_cast<const float2*>(wb + 6 * F)[lane];
    float2 al2 = reinterpret_cast<const float2*>(al)[lane];
    float ri = g_r[node];

    int beg = g_rowptr[node], end = g_rowptr[node + 1];
    float sA = 0.f, aA0 = 0.f, aA1 = 0.f;   // even-edge accumulators
    float sB = 0.f, aB0 = 0.f, aB1 = 0.f;   // odd-edge accumulators

    int p = beg;
    for (; p + 2 <= end; p += 2) {
        int srcA = g_src[p], srcB = g_src[p + 1];
        float4 eA0 = g_ea8[2 * p],     eA1 = g_ea8[2 * p + 1];
        float4 eB0 = g_ea8[2 * p + 2], eB1 = g_ea8[2 * p + 3];
        float2 vA = reinterpret_cast<const float2*>(g_n1 + srcA * F)[lane];
        float2 vB = reinterpret_cast<const float2*>(g_n1 + srcB * F)[lane];

        float cA0 = eA0.x * w0.x + eA0.y * w1v.x + eA0.z * w2v.x + eA0.w * w3v.x
                  + eA1.x * w4v.x + eA1.y * w5v.x + eA1.z * w6v.x;
        float cA1 = eA0.x * w0.y + eA0.y * w1v.y + eA0.z * w2v.y + eA0.w * w3v.y
                  + eA1.x * w4v.y + eA1.y * w5v.y + eA1.z * w6v.y;
        float cB0 = eB0.x * w0.x + eB0.y * w1v.x + eB0.z * w2v.x + eB0.w * w3v.x
                  + eB1.x * w4v.x + eB1.y * w5v.x + eB1.z * w6v.x;
        float cB1 = eB0.x * w0.y + eB0.y * w1v.y + eB0.z * w2v.y + eB0.w * w3v.y
                  + eB1.x * w4v.y + eB1.y * w5v.y + eB1.z * w6v.y;

        float xA0 = lrelu(vA.x + cA0), xA1 = lrelu(vA.y + cA1);
        float xB0 = lrelu(vB.x + cB0), xB1 = lrelu(vB.y + cB1);
        float pA = xA0 * al2.x + xA1 * al2.y;
        float pB = xB0 * al2.x + xB1 * al2.y;
#pragma unroll
        for (int o = 16; o; o >>= 1) {
            pA += __shfl_xor_sync(0xffffffffu, pA, o);
            pB += __shfl_xor_sync(0xffffffffu, pB, o);
        }
        float wA = __expf(lrelu(pA + ri));
        float wB = __expf(lrelu(pB + ri));
        sA += wA;  aA0 = fmaf(wA, xA0, aA0);  aA1 = fmaf(wA, xA1, aA1);
        sB += wB;  aB0 = fmaf(wB, xB0, aB0);  aB1 = fmaf(wB, xB1, aB1);
    }
    if (p < end) {  // remainder (0 or 1 edge)
        int src = g_src[p];
        float4 e0 = g_ea8[2 * p], e1 = g_ea8[2 * p + 1];
        float2 v = reinterpret_cast<const float2*>(g_n1 + src * F)[lane];
        float c0 = e0.x * w0.x + e0.y * w1v.x + e0.z * w2v.x + e0.w * w3v.x
                 + e1.x * w4v.x + e1.y * w5v.x + e1.z * w6v.x;
        float c1 = e0.x * w0.y + e0.y * w1v.y + e0.z * w2v.y + e0.w * w3v.y
                 + e1.x * w4v.y + e1.y * w5v.y + e1.z * w6v.y;
        float x0 = lrelu(v.x + c0), x1 = lrelu(v.y + c1);
        float pp = x0 * al2.x + x1 * al2.y;
#pragma unroll
        for (int o = 16; o; o >>= 1) pp += __shfl_xor_sync(0xffffffffu, pp, o);
        float w = __expf(lrelu(pp + ri));
        sA += w;  aA0 = fmaf(w, x0, aA0);  aA1 = fmaf(w, x1, aA1);
    }
    float inv = 1.f / (sA + sB + 1e-16f);
    reinterpret_cast<float2*>(g_t + node * F)[lane] =
        make_float2((aA0 + aB0) * inv, (aA1 + aB1) * inv);
}

// ---------------- fused: update layer l + prep layer l+1 ----------------
__global__ void k_upprep(const float* __restrict__ w2, const float* __restrict__ b,
                         const float* __restrict__ w1n, const float* __restrict__ arn,
                         int lout) {
    __shared__ float s_w2[F * F];
    __shared__ float s_w1[F * F];
    __shared__ float s_b[F];
    __shared__ float s_ar[F];
    __shared__ float s_x[8][F];
    int tid = threadIdx.x;
    for (int i = tid; i < F * F; i += blockDim.x) { s_w2[i] = w2[i]; s_w1[i] = w1n[i]; }
    if (tid < F) { s_b[tid] = b[tid]; s_ar[tid] = arn[tid]; }
    __syncthreads();
    int warp = tid >> 5, lane = tid & 31;
    int node = blockIdx.x * 8 + warp;
    if (node >= NN) return;
    // stage t
    reinterpret_cast<float2*>(&s_x[warp][0])[lane] =
        reinterpret_cast<const float2*>(g_t + node * F)[lane];
    __syncwarp();
    float2 bb = reinterpret_cast<const float2*>(s_b)[lane];
    float a0 = bb.x, a1 = bb.y;
#pragma unroll 16
    for (int k = 0; k < F; k++) {
        float tv = s_x[warp][k];
        float2 wv = reinterpret_cast<const float2*>(s_w2 + k * F)[lane];
        a0 += tv * wv.x;
        a1 += tv * wv.y;
    }
    float2 h2 = make_float2(fmaxf(a0, 0.f), fmaxf(a1, 0.f));
    reinterpret_cast<float2*>(g_feats[lout] + node * F)[lane] = h2;
    __syncwarp();
    reinterpret_cast<float2*>(&s_x[warp][0])[lane] = h2;
    __syncwarp();
    // prep next layer
    float n0 = 0.f, n1v = 0.f;
#pragma unroll 16
    for (int k = 0; k < F; k++) {
        float hv = s_x[warp][k];
        float2 wv = reinterpret_cast<const float2*>(s_w1 + k * F)[lane];
        n0 += hv * wv.x;
        n1v += hv * wv.y;
    }
    reinterpret_cast<float2*>(g_n1 + node * F)[lane] = make_float2(n0, n1v);
    float2 ar2 = reinterpret_cast<const float2*>(s_ar)[lane];
    float p = h2.x * ar2.x + h2.y * ar2.y;
#pragma unroll
    for (int o = 16; o; o >>= 1) p += __shfl_xor_sync(0xffffffffu, p, o);
    if (lane == 0) g_r[node] = p;
}

// ---------------- fused: update layer2 + head ----------------
__global__ void k_uphead(const float* __restrict__ w2, const float* __restrict__ b,
                         const float* __restrict__ fc1, const float* __restrict__ b1,
                         const float* __restrict__ fc2, const float* __restrict__ b2,
                         float* __restrict__ out) {
    __shared__ float s_w2[F * F];
    __shared__ float s_b[F];
    __shared__ float s_fc1[256 * 20];
    __shared__ float s_fc2[20];
    __shared__ float s_b1[20];
    __shared__ float s_h[8][256];
    int tid = threadIdx.x;
    for (int i = tid; i < F * F; i += blockDim.x) s_w2[i] = w2[i];
    for (int i = tid; i < 256 * 20; i += blockDim.x) s_fc1[i] = fc1[i];
    if (tid < F) s_b[tid] = b[tid];
    if (tid < 20) { s_fc2[tid] = fc2[tid]; s_b1[tid] = b1[tid]; }
    __syncthreads();
    int warp = tid >> 5, lane = tid & 31;
    int node = blockIdx.x * 8 + warp;
    if (node >= NN) return;
    // stage t into s_h[192..255]
    reinterpret_cast<float2*>(&s_h[warp][192])[lane] =
        reinterpret_cast<const float2*>(g_t + node * F)[lane];
    __syncwarp();
    float2 bb = reinterpret_cast<const float2*>(s_b)[lane];
    float a0 = bb.x, a1 = bb.y;
#pragma unroll 16
    for (int k = 0; k < F; k++) {
        float tv = s_h[warp][192 + k];
        float2 wv = reinterpret_cast<const float2*>(s_w2 + k * F)[lane];
        a0 += tv * wv.x;
        a1 += tv * wv.y;
    }
    __syncwarp();
    reinterpret_cast<float2*>(&s_h[warp][192])[lane] =
        make_float2(fmaxf(a0, 0.f), fmaxf(a1, 0.f));
#pragma unroll
    for (int c = 0; c < 3; c++)
        reinterpret_cast<float2*>(&s_h[warp][c * 64])[lane] =
            reinterpret_cast<const float2*>(g_feats[c] + node * F)[lane];
    __syncwarp();
    float z = 0.f;
    if (lane < 20) {
        float z0 = 0.f, z1 = 0.f, z2 = 0.f, z3 = 0.f;
        for (int f = 0; f < 256; f += 4) {
            z0 += s_h[warp][f]     * s_fc1[f * 20 + lane];
            z1 += s_h[warp][f + 1] * s_fc1[(f + 1) * 20 + lane];
            z2 += s_h[warp][f + 2] * s_fc1[(f + 2) * 20 + lane];
            z3 += s_h[warp][f + 3] * s_fc1[(f + 3) * 20 + lane];
        }
        z = s_b1[lane] + (z0 + z1) + (z2 + z3);
        z = fmaxf(z, 0.f) * s_fc2[lane];
    }
#pragma unroll
    for (int o = 16; o; o >>= 1) z += __shfl_xor_sync(0xffffffffu, z, o);
    if (lane == 0) out[node] = 1.f / (1.f + __expf(-(z + b2[0])));
}

// ---------------- launch ----------------
extern "C" void kernel_launch(void* const* d_in, const int* in_sizes, int n_in,
                              void* d_out, int out_size) {
    const int*   x     = (const int*)  d_in[0];
    const int*   ei    = (const int*)  d_in[1];   // [2, E]
    const float* eattr = (const float*)d_in[2];   // [E, 7]
    const float* emb   = (const float*)d_in[3];   // [VOCAB, 64]
    const float* lin1  = (const float*)d_in[4];   // [3, 71, 64]
    const float* attl  = (const float*)d_in[5];   // [3, 64]
    const float* attr_ = (const float*)d_in[6];   // [3, 64]
    const float* lin2  = (const float*)d_in[7];   // [3, 64, 64]
    const float* gb    = (const float*)d_in[8];   // [3, 64]
    const float* fc1   = (const float*)d_in[9];   // [256, 20]
    const float* fb1   = (const float*)d_in[10];  // [20]
    const float* fc2   = (const float*)d_in[11];  // [20, 1]
    const float* fb2   = (const float*)d_in[12];  // [1]
    float* out = (float*)d_out;

    int nb = (NN + 7) / 8;  // warp per node, 8 warps/block

    k_hist<<<(NE + 255) / 256, 256>>>(ei);
    k_scan_a<<<NSB, SCAN_BS>>>();
    k_scan_b<<<1, 128>>>();
    k_scan_c<<<NSB, SCAN_BS>>>();
    k_scatter<<<(NE + 255) / 256, 256>>>(ei, eattr);
    k_gprep<<<nb, 256>>>(x, emb, lin1, attr_);

    k_edge<<<nb, 256>>>(lin1, attl);
    k_upprep<<<nb, 256>>>(lin2, gb, lin1 + 1 * 71 * F, attr_ + 1 * F, 1);
    k_edge<<<nb, 256>>>(lin1 + 1 * 71 * F, attl + 1 * F);
    k_upprep<<<nb, 256>>>(lin2 + 1 * F * F, gb + 1 * F, lin1 + 2 * 71 * F, attr_ + 2 * F, 2);
    k_edge<<<nb, 256>>>(lin1 + 2 * 71 * F, attl + 2 * F);
    k_uphead<<<nb, 256>>>(lin2 + 2 * F * F, gb + 2 * F, fc1, fb1, fc2, fb2, out);
}